// round 11
// baseline (speedup 1.0000x reference)
#include <cuda_runtime.h>
#include <cstdint>
#include <cstddef>

typedef unsigned long long ull;

#define BB 4096
#define TT 256
#define DD 64
#define HH 32
#define BT (BB * TT)

// Scratch: A[b,t,j] = b1[j] + sum_{k<64} states[b,t,k] * W1[k][j]   (128 MiB)
__device__ float g_A[(size_t)BT * 32];

// ---------- packed f32x2 helpers ----------
static __device__ __forceinline__ ull pack2(float lo, float hi) {
    ull r;
    asm("mov.b64 %0, {%1, %2};" : "=l"(r) : "f"(lo), "f"(hi));
    return r;
}
static __device__ __forceinline__ void unpack2(ull v, float& lo, float& hi) {
    asm("mov.b64 {%0, %1}, %2;" : "=f"(lo), "=f"(hi) : "l"(v));
}
static __device__ __forceinline__ void ffma2(ull& acc, ull a, ull b) {
    asm("fma.rn.f32x2 %0, %1, %2, %0;" : "+l"(acc) : "l"(a), "l"(b));
}
static __device__ __forceinline__ ull addx2(ull a, ull b) {
    ull r;
    asm("add.rn.f32x2 %0, %1, %2;" : "=l"(r) : "l"(a), "l"(b));
    return r;
}
static __device__ __forceinline__ void lds_v2u64(ull& a, ull& b, uint32_t addr) {
    asm volatile("ld.shared.v2.b64 {%0, %1}, [%2];" : "=l"(a), "=l"(b) : "r"(addr) : "memory");
}
static __device__ __forceinline__ void sts_f32(uint32_t addr, float v) {
    asm volatile("st.shared.f32 [%0], %1;" :: "r"(addr), "f"(v) : "memory");
}
static __device__ __forceinline__ uint32_t smem_u32(const void* p) {
    return (uint32_t)__cvta_generic_to_shared(p);
}
// cp.async 4B global->shared
static __device__ __forceinline__ void cp_async4(uint32_t dst, const float* src) {
    asm volatile("cp.async.ca.shared.global [%0], [%1], 4;" :: "r"(dst), "l"(src) : "memory");
}
static __device__ __forceinline__ void cp_commit() {
    asm volatile("cp.async.commit_group;" ::: "memory");
}
static __device__ __forceinline__ void cp_wait1() {
    asm volatile("cp.async.wait_group 1;" ::: "memory");
}

// ============================================================================
// Kernel 1: A = states @ W1[:64,:] + b1   (unchanged from R10: 175.7 us)
// ============================================================================
#define PT_ROWS 128
#define ST 66  // ull stride per k (64 rps + 2 pad)

__global__ void __launch_bounds__(256) precompute_kernel(const float* __restrict__ states,
                                                         const float* __restrict__ W1,
                                                         const float* __restrict__ b1) {
    __shared__ __align__(16) ull stp[64 * ST];
    __shared__ float W1s[64 * 32];

    int tid = threadIdx.x;
    size_t row0 = (size_t)blockIdx.x * PT_ROWS;

    for (int i = tid; i < 64 * 32; i += 256) W1s[i] = W1[i];

    {
        int rp = tid >> 2;
        int ks = tid & 3;
        const float* base = states + (row0 + 2 * (size_t)rp) * 64;
#pragma unroll
        for (int h = 0; h < 4; h++) {
            int k4 = ks + 4 * h;
            float4 fa = *(const float4*)(base + k4 * 4);
            float4 fb = *(const float4*)(base + 64 + k4 * 4);
            stp[(k4 * 4 + 0) * ST + rp] = pack2(fa.x, fb.x);
            stp[(k4 * 4 + 1) * ST + rp] = pack2(fa.y, fb.y);
            stp[(k4 * 4 + 2) * ST + rp] = pack2(fa.z, fb.z);
            stp[(k4 * 4 + 3) * ST + rp] = pack2(fa.w, fb.w);
        }
    }
    __syncthreads();

    int w = tid >> 5;
    int j = tid & 31;

    ull acc[8];
#pragma unroll
    for (int i = 0; i < 8; i++) acc[i] = 0;
    uint32_t stp_base = smem_u32(stp);

#pragma unroll 1
    for (int ch = 0; ch < 2; ch++) {
        ull wd[32];
#pragma unroll
        for (int kk = 0; kk < 32; kk++) {
            float wv = W1s[(32 * ch + kk) * 32 + j];
            wd[kk] = pack2(wv, wv);
        }
#pragma unroll
        for (int kk = 0; kk < 32; kk++) {
            int k = 32 * ch + kk;
            uint32_t a = stp_base + (k * ST + 8 * w) * 8;
            ull p0, p1, p2, p3, p4, p5, p6, p7;
            lds_v2u64(p0, p1, a);
            lds_v2u64(p2, p3, a + 16);
            lds_v2u64(p4, p5, a + 32);
            lds_v2u64(p6, p7, a + 48);
            ffma2(acc[0], p0, wd[kk]);
            ffma2(acc[1], p1, wd[kk]);
            ffma2(acc[2], p2, wd[kk]);
            ffma2(acc[3], p3, wd[kk]);
            ffma2(acc[4], p4, wd[kk]);
            ffma2(acc[5], p5, wd[kk]);
            ffma2(acc[6], p6, wd[kk]);
            ffma2(acc[7], p7, wd[kk]);
        }
    }

    float bj = __ldg(&b1[j]);
    float* gp = g_A + (row0 + 16 * (size_t)w) * 32 + j;
#pragma unroll
    for (int i = 0; i < 8; i++) {
        float lo, hi;
        unpack2(acc[i], lo, hi);
        gp[(2 * i) * 32] = bj + lo;
        gp[(2 * i + 1) * 32] = bj + hi;
    }
}

// ============================================================================
// Kernel 2: recurrence. Block = 64 thr = 2 warps, 2 chains per warp (R9
// structure). NEW vs R9:
//  - A and gumbel staged into smem via cp.async, 4-step chunks, double
//    buffered, issued 2 chunks (8 steps) ahead -> DRAM latency off the
//    serial chain; consumption = lane-private LDS (no extra syncs needed).
//  - argmax via sortable-uint key + __reduce_max_sync (per-8-lane-group
//    mask) + one full-warp ballot; all 4 group winners extracted locally
//    with ffs (lowest-lane = first-index tie-break, bit-exact).
//  - step loop kept ROLLED (L0 I$ fits; lesson from R10).
// ============================================================================
#define CH 4  // steps per staging chunk

static __device__ __forceinline__ float matvec32(uint32_t base, const ull* Wp, float bias) {
    ull a0 = 0, a1 = 0, a2 = 0, a3 = 0;
#pragma unroll
    for (int l = 0; l < 8; l++) {
        ull p0, p1;
        lds_v2u64(p0, p1, base + l * 16);
        if (l & 1) {
            ffma2(a2, p0, Wp[2 * l]);
            ffma2(a3, p1, Wp[2 * l + 1]);
        } else {
            ffma2(a0, p0, Wp[2 * l]);
            ffma2(a1, p1, Wp[2 * l + 1]);
        }
    }
    ull s = addx2(addx2(a0, a2), addx2(a1, a3));
    float lo, hi;
    unpack2(s, lo, hi);
    return bias + (lo + hi);
}

// monotone fp32 -> u32 key (order-preserving, exact)
static __device__ __forceinline__ unsigned sortable(float v) {
    unsigned u = __float_as_uint(v);
    u ^= ((unsigned)((int)u >> 31)) | 0x80000000u;
    return u;
}

__global__ void __launch_bounds__(64) recur_kernel(const float* __restrict__ gumbel,
                                                   const float* __restrict__ W1,
                                                   const float* __restrict__ W2,
                                                   const float* __restrict__ b2,
                                                   const float* __restrict__ W3,
                                                   const float* __restrict__ b3,
                                                   float* __restrict__ out) {
    __shared__ float W1c[32 * 32];                    // rows 64..95 of W1
    __shared__ __align__(16) float bufx[2][2][32];    // [warp][chain][32] : h1
    __shared__ __align__(16) float bufy[2][2][32];    // h2
    __shared__ __align__(16) float sA[2][2][2][CH][32];  // [warp][buf][chain][p][lane]
    __shared__ __align__(16) float sG[2][2][2][CH][32];

    int tid = threadIdx.x;
    for (int i = tid; i < 32 * 32; i += 64) W1c[i] = W1[64 * 32 + i];
    __syncthreads();

    const unsigned FULL = 0xffffffffu;
    int w = tid >> 5;
    int j = tid & 31;
    int jg = j & 7;
    unsigned gsh = (unsigned)(j & 24);          // 8 * group
    unsigned gmask = 0xFFu << gsh;              // this lane's 8-lane group mask

    ull W2p[16], W3p[16];
#pragma unroll
    for (int i = 0; i < 16; i++) {
        W2p[i] = pack2(__ldg(&W2[(2 * i) * 32 + j]), __ldg(&W2[(2 * i + 1) * 32 + j]));
        W3p[i] = pack2(__ldg(&W3[(2 * i) * 32 + j]), __ldg(&W3[(2 * i + 1) * 32 + j]));
    }
    float b2j = __ldg(&b2[j]);
    float b3j = __ldg(&b3[j]);

    uint32_t bx[2], by[2], bxj[2], byj[2];
#pragma unroll
    for (int c = 0; c < 2; c++) {
        bx[c] = smem_u32(&bufx[w][c][0]);
        by[c] = smem_u32(&bufy[w][c][0]);
        bxj[c] = bx[c] + 4 * j;
        byj[c] = by[c] + 4 * j;
    }

    const float* Ap[2];
    const float* Gp[2];
    float* Op[2];
    int i0[2], i1[2], i2[2], i3[2];
    uint32_t sAa[2][2], sGa[2][2];  // [buf][chain] smem dst base (+4j)

#pragma unroll
    for (int c = 0; c < 2; c++) {
        int b = blockIdx.x * 4 + 2 * w + c;
        size_t base = ((size_t)b * TT) * 32 + j;
        Ap[c] = g_A + base;
        Gp[c] = gumbel + base;
        Op[c] = out + base;
        i0[c] = i1[c] = i2[c] = i3[c] = 0;
#pragma unroll
        for (int bf = 0; bf < 2; bf++) {
            sAa[bf][c] = smem_u32(&sA[w][bf][c][0][0]) + 4 * j;
            sGa[bf][c] = smem_u32(&sG[w][bf][c][0][0]) + 4 * j;
        }
    }

    // stage chunk at t0 into buffer bf (clamped at tail; lane-private slots)
    auto stage = [&](int bf, int t0) {
#pragma unroll
        for (int c = 0; c < 2; c++) {
#pragma unroll
            for (int p = 0; p < CH; p++) {
                int tt = t0 + p;
                if (tt > TT - 1) tt = TT - 1;
                cp_async4(sAa[bf][c] + p * 128, Ap[c] + tt * 32);
                cp_async4(sGa[bf][c] + p * 128, Gp[c] + tt * 32);
            }
        }
    };

    stage(0, 0);
    cp_commit();
    stage(1, CH);
    cp_commit();

    int ib = 0;
#pragma unroll 1
    for (int tc = 0; tc < TT; tc += CH, ib ^= 1) {
        cp_wait1();  // the buffer for this chunk is complete

#pragma unroll 1
        for (int p = 0; p < CH; p++) {
            // lane-private staged inputs (written by this lane's cp.async)
            float a_c[2], g_c[2];
#pragma unroll
            for (int c = 0; c < 2; c++) {
                a_c[c] = sA[w][ib][c][p][j];
                g_c[c] = sG[w][ib][c][p][j];
            }

            // fc1 (+relu), stage h1
#pragma unroll
            for (int c = 0; c < 2; c++) {
                float h1 = a_c[c] + W1c[i0[c] * 32 + j] + W1c[(8 + i1[c]) * 32 + j] +
                           W1c[(16 + i2[c]) * 32 + j] + W1c[(24 + i3[c]) * 32 + j];
                h1 = fmaxf(h1, 0.0f);
                sts_f32(bxj[c], h1);
            }
            __syncwarp();

            // fc2 (+relu), stage h2
            float h2v[2];
#pragma unroll
            for (int c = 0; c < 2; c++)
                h2v[c] = fmaxf(matvec32(bx[c], W2p, b2j), 0.0f);
#pragma unroll
            for (int c = 0; c < 2; c++) sts_f32(byj[c], h2v[c]);
            __syncwarp();

            // fc3 + gumbel (softmax & /tau strictly monotone -> argmax only)
#pragma unroll
            for (int c = 0; c < 2; c++) {
                float v = matvec32(by[c], W3p, b3j) + g_c[c];

                // segmented argmax over the lane's 8-lane group:
                // exact key, group max via redux, winners via one ballot.
                unsigned u = sortable(v);
                unsigned m = __reduce_max_sync(gmask, u);
                unsigned bal = __ballot_sync(FULL, u == m);

                int win = __ffs((bal >> gsh) & 0xFFu) - 1;  // lowest lane = first index
                // straight-through forward == exact hard one-hot
                Op[c][(tc + p) * 32] = (win == jg) ? 1.0f : 0.0f;

                // all 4 group winners from the (uniform) ballot, no shuffles
                i0[c] = __ffs(bal & 0xFFu) - 1;
                i1[c] = __ffs((bal >> 8) & 0xFFu) - 1;
                i2[c] = __ffs((bal >> 16) & 0xFFu) - 1;
                i3[c] = __ffs((bal >> 24) & 0xFFu) - 1;
            }
        }

        // refill the buffer just consumed, 2 chunks ahead
        stage(ib, tc + 2 * CH);
        cp_commit();
    }
}

// ============================================================================
// Launch
// ============================================================================
extern "C" void kernel_launch(void* const* d_in, const int* in_sizes, int n_in,
                              void* d_out, int out_size) {
    const float* states = (const float*)d_in[0];  // [B,T,64]
    const float* gumbel = (const float*)d_in[1];  // [B,T,4,8]
    // d_in[2] = tau (unused: monotone under argmax)
    const float* W1     = (const float*)d_in[3];  // [96,32]
    const float* b1     = (const float*)d_in[4];  // [32]
    const float* W2     = (const float*)d_in[5];  // [32,32]
    const float* b2     = (const float*)d_in[6];  // [32]
    const float* W3     = (const float*)d_in[7];  // [32,32]
    const float* b3     = (const float*)d_in[8];  // [32]
    float* out = (float*)d_out;                   // [B,T,32]

    precompute_kernel<<<BT / PT_ROWS, 256>>>(states, W1, b1);
    recur_kernel<<<BB / 4, 64>>>(gumbel, W1, W2, b2, W3, b3, out);
}

// round 12
// speedup vs baseline: 1.3850x; 1.3850x over previous
#include <cuda_runtime.h>
#include <cstdint>
#include <cstddef>

typedef unsigned long long ull;

#define BB 4096
#define TT 256
#define DD 64
#define HH 32
#define BT (BB * TT)

// Scratch: A[b,t,j] = b1[j] + sum_{k<64} states[b,t,k] * W1[k][j]   (128 MiB)
__device__ float g_A[(size_t)BT * 32];

// ---------- packed f32x2 helpers ----------
static __device__ __forceinline__ ull pack2(float lo, float hi) {
    ull r;
    asm("mov.b64 %0, {%1, %2};" : "=l"(r) : "f"(lo), "f"(hi));
    return r;
}
static __device__ __forceinline__ void unpack2(ull v, float& lo, float& hi) {
    asm("mov.b64 {%0, %1}, %2;" : "=f"(lo), "=f"(hi) : "l"(v));
}
static __device__ __forceinline__ void ffma2(ull& acc, ull a, ull b) {
    asm("fma.rn.f32x2 %0, %1, %2, %0;" : "+l"(acc) : "l"(a), "l"(b));
}
static __device__ __forceinline__ ull addx2(ull a, ull b) {
    ull r;
    asm("add.rn.f32x2 %0, %1, %2;" : "=l"(r) : "l"(a), "l"(b));
    return r;
}
static __device__ __forceinline__ void lds_v2u64(ull& a, ull& b, uint32_t addr) {
    asm volatile("ld.shared.v2.b64 {%0, %1}, [%2];" : "=l"(a), "=l"(b) : "r"(addr) : "memory");
}
static __device__ __forceinline__ void sts_f32(uint32_t addr, float v) {
    asm volatile("st.shared.f32 [%0], %1;" :: "r"(addr), "f"(v) : "memory");
}
static __device__ __forceinline__ uint32_t smem_u32(const void* p) {
    return (uint32_t)__cvta_generic_to_shared(p);
}

// ============================================================================
// Kernel 1: A = states @ W1[:64,:] + b1   (unchanged: measured 175.7 us)
// ============================================================================
#define PT_ROWS 128
#define ST 66  // ull stride per k (64 rps + 2 pad)

__global__ void __launch_bounds__(256) precompute_kernel(const float* __restrict__ states,
                                                         const float* __restrict__ W1,
                                                         const float* __restrict__ b1) {
    __shared__ __align__(16) ull stp[64 * ST];
    __shared__ float W1s[64 * 32];

    int tid = threadIdx.x;
    size_t row0 = (size_t)blockIdx.x * PT_ROWS;

    for (int i = tid; i < 64 * 32; i += 256) W1s[i] = W1[i];

    {
        int rp = tid >> 2;
        int ks = tid & 3;
        const float* base = states + (row0 + 2 * (size_t)rp) * 64;
#pragma unroll
        for (int h = 0; h < 4; h++) {
            int k4 = ks + 4 * h;
            float4 fa = *(const float4*)(base + k4 * 4);
            float4 fb = *(const float4*)(base + 64 + k4 * 4);
            stp[(k4 * 4 + 0) * ST + rp] = pack2(fa.x, fb.x);
            stp[(k4 * 4 + 1) * ST + rp] = pack2(fa.y, fb.y);
            stp[(k4 * 4 + 2) * ST + rp] = pack2(fa.z, fb.z);
            stp[(k4 * 4 + 3) * ST + rp] = pack2(fa.w, fb.w);
        }
    }
    __syncthreads();

    int w = tid >> 5;
    int j = tid & 31;

    ull acc[8];
#pragma unroll
    for (int i = 0; i < 8; i++) acc[i] = 0;
    uint32_t stp_base = smem_u32(stp);

#pragma unroll 1
    for (int ch = 0; ch < 2; ch++) {
        ull wd[32];
#pragma unroll
        for (int kk = 0; kk < 32; kk++) {
            float wv = W1s[(32 * ch + kk) * 32 + j];
            wd[kk] = pack2(wv, wv);
        }
#pragma unroll
        for (int kk = 0; kk < 32; kk++) {
            int k = 32 * ch + kk;
            uint32_t a = stp_base + (k * ST + 8 * w) * 8;
            ull p0, p1, p2, p3, p4, p5, p6, p7;
            lds_v2u64(p0, p1, a);
            lds_v2u64(p2, p3, a + 16);
            lds_v2u64(p4, p5, a + 32);
            lds_v2u64(p6, p7, a + 48);
            ffma2(acc[0], p0, wd[kk]);
            ffma2(acc[1], p1, wd[kk]);
            ffma2(acc[2], p2, wd[kk]);
            ffma2(acc[3], p3, wd[kk]);
            ffma2(acc[4], p4, wd[kk]);
            ffma2(acc[5], p5, wd[kk]);
            ffma2(acc[6], p6, wd[kk]);
            ffma2(acc[7], p7, wd[kk]);
        }
    }

    float bj = __ldg(&b1[j]);
    float* gp = g_A + (row0 + 16 * (size_t)w) * 32 + j;
#pragma unroll
    for (int i = 0; i < 8; i++) {
        float lo, hi;
        unpack2(acc[i], lo, hi);
        gp[(2 * i) * 32] = bj + lo;
        gp[(2 * i + 1) * 32] = bj + hi;
    }
}

// ============================================================================
// Kernel 2: recurrence. Block = 64 thr = 2 warps, 2 chains per warp (R9
// structure, measured 257 us). Changes vs R9:
//  - depth-2 REGISTER prefetch: outer t-loop steps by 2, inner parity loop
//    fully unrolled (x2 only). a_buf[par]/g_buf[par] are consumed then
//    refilled for t+2 -> each LDG gets ~2 full steps of latency cover.
//    Zero extra instructions (no MOV rotation, no smem staging).
//  - redux+ballot argmax (validated bit-exact in R11): sortable-u32 key,
//    __reduce_max_sync over the 8-lane group, one full-warp ballot; all 4
//    group winners extracted locally via ffs (lowest lane = first index).
// ============================================================================
static __device__ __forceinline__ float matvec32(uint32_t base, const ull* Wp, float bias) {
    ull a0 = 0, a1 = 0, a2 = 0, a3 = 0;
#pragma unroll
    for (int l = 0; l < 8; l++) {
        ull p0, p1;
        lds_v2u64(p0, p1, base + l * 16);
        if (l & 1) {
            ffma2(a2, p0, Wp[2 * l]);
            ffma2(a3, p1, Wp[2 * l + 1]);
        } else {
            ffma2(a0, p0, Wp[2 * l]);
            ffma2(a1, p1, Wp[2 * l + 1]);
        }
    }
    ull s = addx2(addx2(a0, a2), addx2(a1, a3));
    float lo, hi;
    unpack2(s, lo, hi);
    return bias + (lo + hi);
}

// monotone fp32 -> u32 key (order-preserving, exact)
static __device__ __forceinline__ unsigned sortable(float v) {
    unsigned u = __float_as_uint(v);
    u ^= ((unsigned)((int)u >> 31)) | 0x80000000u;
    return u;
}

__global__ void __launch_bounds__(64) recur_kernel(const float* __restrict__ gumbel,
                                                   const float* __restrict__ W1,
                                                   const float* __restrict__ W2,
                                                   const float* __restrict__ b2,
                                                   const float* __restrict__ W3,
                                                   const float* __restrict__ b3,
                                                   float* __restrict__ out) {
    __shared__ float W1c[32 * 32];                    // rows 64..95 of W1
    __shared__ __align__(16) float bufx[2][2][32];    // [warp][chain][32] : h1
    __shared__ __align__(16) float bufy[2][2][32];    // h2

    int tid = threadIdx.x;
    for (int i = tid; i < 32 * 32; i += 64) W1c[i] = W1[64 * 32 + i];
    __syncthreads();

    const unsigned FULL = 0xffffffffu;
    int w = tid >> 5;
    int j = tid & 31;
    int jg = j & 7;
    unsigned gsh = (unsigned)(j & 24);          // 8 * group index
    unsigned gmask = 0xFFu << gsh;              // this lane's 8-lane group

    ull W2p[16], W3p[16];
#pragma unroll
    for (int i = 0; i < 16; i++) {
        W2p[i] = pack2(__ldg(&W2[(2 * i) * 32 + j]), __ldg(&W2[(2 * i + 1) * 32 + j]));
        W3p[i] = pack2(__ldg(&W3[(2 * i) * 32 + j]), __ldg(&W3[(2 * i + 1) * 32 + j]));
    }
    float b2j = __ldg(&b2[j]);
    float b3j = __ldg(&b3[j]);

    uint32_t bx[2], by[2], bxj[2], byj[2];
#pragma unroll
    for (int c = 0; c < 2; c++) {
        bx[c] = smem_u32(&bufx[w][c][0]);
        by[c] = smem_u32(&bufy[w][c][0]);
        bxj[c] = bx[c] + 4 * j;
        byj[c] = by[c] + 4 * j;
    }

    const float* Ap[2];
    const float* Gp[2];
    float* Op[2];
    int i0[2], i1[2], i2[2], i3[2];
    float a_buf[2][2], g_buf[2][2];  // [parity][chain]

#pragma unroll
    for (int c = 0; c < 2; c++) {
        int b = blockIdx.x * 4 + 2 * w + c;
        size_t base = ((size_t)b * TT) * 32 + j;
        Ap[c] = g_A + base;
        Gp[c] = gumbel + base;
        Op[c] = out + base;
        i0[c] = i1[c] = i2[c] = i3[c] = 0;
        a_buf[0][c] = Ap[c][0];
        g_buf[0][c] = Gp[c][0];
        a_buf[1][c] = Ap[c][32];
        g_buf[1][c] = Gp[c][32];
    }

#pragma unroll 1
    for (int t = 0; t < TT; t += 2) {
#pragma unroll
        for (int par = 0; par < 2; par++) {
            int tn = t + par + 2;
            if (tn > TT - 1) tn = TT - 1;  // clamped redundant refill, no branch

            // fc1 (+relu) consumes a_buf[par]; stage h1
#pragma unroll
            for (int c = 0; c < 2; c++) {
                float h1 = a_buf[par][c] + W1c[i0[c] * 32 + j] + W1c[(8 + i1[c]) * 32 + j] +
                           W1c[(16 + i2[c]) * 32 + j] + W1c[(24 + i3[c]) * 32 + j];
                h1 = fmaxf(h1, 0.0f);
                sts_f32(bxj[c], h1);
            }
            // refill a for step t+par+2 (2 full steps of cover)
#pragma unroll
            for (int c = 0; c < 2; c++) a_buf[par][c] = Ap[c][tn * 32];
            __syncwarp();

            // fc2 (+relu), stage h2
            float h2v[2];
#pragma unroll
            for (int c = 0; c < 2; c++)
                h2v[c] = fmaxf(matvec32(bx[c], W2p, b2j), 0.0f);
#pragma unroll
            for (int c = 0; c < 2; c++) sts_f32(byj[c], h2v[c]);
            __syncwarp();

            // fc3 + gumbel (softmax & /tau strictly monotone -> argmax only)
#pragma unroll
            for (int c = 0; c < 2; c++) {
                float v = matvec32(by[c], W3p, b3j) + g_buf[par][c];

                unsigned u = sortable(v);
                unsigned m = __reduce_max_sync(gmask, u);
                unsigned bal = __ballot_sync(FULL, u == m);

                int win = __ffs((bal >> gsh) & 0xFFu) - 1;  // lowest lane = first index
                // straight-through forward == exact hard one-hot
                Op[c][(t + par) * 32] = (win == jg) ? 1.0f : 0.0f;

                // all 4 group winners from the uniform ballot, no shuffles
                i0[c] = __ffs(bal & 0xFFu) - 1;
                i1[c] = __ffs((bal >> 8) & 0xFFu) - 1;
                i2[c] = __ffs((bal >> 16) & 0xFFu) - 1;
                i3[c] = __ffs((bal >> 24) & 0xFFu) - 1;
            }
            // refill g AFTER its use in fc3 (WAR-safe), same 2-step cover
#pragma unroll
            for (int c = 0; c < 2; c++) g_buf[par][c] = Gp[c][tn * 32];
        }
    }
}

// ============================================================================
// Launch
// ============================================================================
extern "C" void kernel_launch(void* const* d_in, const int* in_sizes, int n_in,
                              void* d_out, int out_size) {
    const float* states = (const float*)d_in[0];  // [B,T,64]
    const float* gumbel = (const float*)d_in[1];  // [B,T,4,8]
    // d_in[2] = tau (unused: monotone under argmax)
    const float* W1     = (const float*)d_in[3];  // [96,32]
    const float* b1     = (const float*)d_in[4];  // [32]
    const float* W2     = (const float*)d_in[5];  // [32,32]
    const float* b2     = (const float*)d_in[6];  // [32]
    const float* W3     = (const float*)d_in[7];  // [32,32]
    const float* b3     = (const float*)d_in[8];  // [32]
    float* out = (float*)d_out;                   // [B,T,32]

    precompute_kernel<<<BT / PT_ROWS, 256>>>(states, W1, b1);
    recur_kernel<<<BB / 4, 64>>>(gumbel, W1, W2, b2, W3, b3, out);
}

// round 13
// speedup vs baseline: 1.6950x; 1.2238x over previous
#include <cuda_runtime.h>
#include <cstdint>
#include <cstddef>

typedef unsigned long long ull;

#define BB 4096
#define TT 256
#define DD 64
#define HH 32
#define BT (BB * TT)

// Scratch: A[b,t,j] = b1[j] + sum_{k<64} states[b,t,k] * W1[k][j]   (128 MiB)
__device__ float g_A[(size_t)BT * 32];

// ---------- packed f32x2 helpers ----------
static __device__ __forceinline__ ull pack2(float lo, float hi) {
    ull r;
    asm("mov.b64 %0, {%1, %2};" : "=l"(r) : "f"(lo), "f"(hi));
    return r;
}
static __device__ __forceinline__ void unpack2(ull v, float& lo, float& hi) {
    asm("mov.b64 {%0, %1}, %2;" : "=f"(lo), "=f"(hi) : "l"(v));
}
static __device__ __forceinline__ void ffma2(ull& acc, ull a, ull b) {
    asm("fma.rn.f32x2 %0, %1, %2, %0;" : "+l"(acc) : "l"(a), "l"(b));
}
static __device__ __forceinline__ ull addx2(ull a, ull b) {
    ull r;
    asm("add.rn.f32x2 %0, %1, %2;" : "=l"(r) : "l"(a), "l"(b));
    return r;
}
static __device__ __forceinline__ void lds_v2u64(ull& a, ull& b, uint32_t addr) {
    asm volatile("ld.shared.v2.b64 {%0, %1}, [%2];" : "=l"(a), "=l"(b) : "r"(addr) : "memory");
}
static __device__ __forceinline__ void sts_f32(uint32_t addr, float v) {
    asm volatile("st.shared.f32 [%0], %1;" :: "r"(addr), "f"(v) : "memory");
}
static __device__ __forceinline__ uint32_t smem_u32(const void* p) {
    return (uint32_t)__cvta_generic_to_shared(p);
}

// ============================================================================
// Kernel 1: A = states @ W1[:64,:] + b1   (unchanged: measured 175.7 us)
// ============================================================================
#define PT_ROWS 128
#define ST 66  // ull stride per k (64 rps + 2 pad)

__global__ void __launch_bounds__(256) precompute_kernel(const float* __restrict__ states,
                                                         const float* __restrict__ W1,
                                                         const float* __restrict__ b1) {
    __shared__ __align__(16) ull stp[64 * ST];
    __shared__ float W1s[64 * 32];

    int tid = threadIdx.x;
    size_t row0 = (size_t)blockIdx.x * PT_ROWS;

    for (int i = tid; i < 64 * 32; i += 256) W1s[i] = W1[i];

    {
        int rp = tid >> 2;
        int ks = tid & 3;
        const float* base = states + (row0 + 2 * (size_t)rp) * 64;
#pragma unroll
        for (int h = 0; h < 4; h++) {
            int k4 = ks + 4 * h;
            float4 fa = *(const float4*)(base + k4 * 4);
            float4 fb = *(const float4*)(base + 64 + k4 * 4);
            stp[(k4 * 4 + 0) * ST + rp] = pack2(fa.x, fb.x);
            stp[(k4 * 4 + 1) * ST + rp] = pack2(fa.y, fb.y);
            stp[(k4 * 4 + 2) * ST + rp] = pack2(fa.z, fb.z);
            stp[(k4 * 4 + 3) * ST + rp] = pack2(fa.w, fb.w);
        }
    }
    __syncthreads();

    int w = tid >> 5;
    int j = tid & 31;

    ull acc[8];
#pragma unroll
    for (int i = 0; i < 8; i++) acc[i] = 0;
    uint32_t stp_base = smem_u32(stp);

#pragma unroll 1
    for (int ch = 0; ch < 2; ch++) {
        ull wd[32];
#pragma unroll
        for (int kk = 0; kk < 32; kk++) {
            float wv = W1s[(32 * ch + kk) * 32 + j];
            wd[kk] = pack2(wv, wv);
        }
#pragma unroll
        for (int kk = 0; kk < 32; kk++) {
            int k = 32 * ch + kk;
            uint32_t a = stp_base + (k * ST + 8 * w) * 8;
            ull p0, p1, p2, p3, p4, p5, p6, p7;
            lds_v2u64(p0, p1, a);
            lds_v2u64(p2, p3, a + 16);
            lds_v2u64(p4, p5, a + 32);
            lds_v2u64(p6, p7, a + 48);
            ffma2(acc[0], p0, wd[kk]);
            ffma2(acc[1], p1, wd[kk]);
            ffma2(acc[2], p2, wd[kk]);
            ffma2(acc[3], p3, wd[kk]);
            ffma2(acc[4], p4, wd[kk]);
            ffma2(acc[5], p5, wd[kk]);
            ffma2(acc[6], p6, wd[kk]);
            ffma2(acc[7], p7, wd[kk]);
        }
    }

    float bj = __ldg(&b1[j]);
    float* gp = g_A + (row0 + 16 * (size_t)w) * 32 + j;
#pragma unroll
    for (int i = 0; i < 8; i++) {
        float lo, hi;
        unpack2(acc[i], lo, hi);
        gp[(2 * i) * 32] = bj + lo;
        gp[(2 * i + 1) * 32] = bj + hi;
    }
}

// ============================================================================
// Kernel 2: recurrence. ONE chain per warp (in-order issue serialized R9's
// two chains -> L was ~2x single-chain path; this halves L). Block = 64 thr
// = 2 warps. Matvec: h staged to per-warp smem, 8x ld.shared.v2.b64 + 16
// FFMA2 vs register-resident packed weight pairs (weights MUST be registers:
// smem weights at 28 warps/SM would crossbar-saturate).
// Argmax: fmax-only butterfly (3 shfl) + one ballot; all 4 group winners via
// ffs on the uniform ballot (lowest lane = first index, bit-exact).
// Depth-2 parity register prefetch (body ~1.9KB, x2 unroll fits L0 I$).
// ============================================================================
static __device__ __forceinline__ float matvec32(uint32_t base, const ull* Wp, float bias) {
    ull a0 = 0, a1 = 0, a2 = 0, a3 = 0;
#pragma unroll
    for (int l = 0; l < 8; l++) {
        ull p0, p1;
        lds_v2u64(p0, p1, base + l * 16);
        if (l & 1) {
            ffma2(a2, p0, Wp[2 * l]);
            ffma2(a3, p1, Wp[2 * l + 1]);
        } else {
            ffma2(a0, p0, Wp[2 * l]);
            ffma2(a1, p1, Wp[2 * l + 1]);
        }
    }
    ull s = addx2(addx2(a0, a2), addx2(a1, a3));
    float lo, hi;
    unpack2(s, lo, hi);
    return bias + (lo + hi);
}

__global__ void __launch_bounds__(64) recur_kernel(const float* __restrict__ gumbel,
                                                   const float* __restrict__ W1,
                                                   const float* __restrict__ W2,
                                                   const float* __restrict__ b2,
                                                   const float* __restrict__ W3,
                                                   const float* __restrict__ b3,
                                                   float* __restrict__ out) {
    __shared__ float W1c[32 * 32];                    // rows 64..95 of W1
    __shared__ __align__(16) float bufx[2][32];       // [warp][32] : h1
    __shared__ __align__(16) float bufy[2][32];       // h2

    int tid = threadIdx.x;
    for (int i = tid; i < 32 * 32; i += 64) W1c[i] = W1[64 * 32 + i];
    __syncthreads();

    const unsigned FULL = 0xffffffffu;
    int w = tid >> 5;
    int j = tid & 31;
    int jg = j & 7;
    unsigned gsh = (unsigned)(j & 24);  // 8 * group index

    // register-resident packed weight pairs
    ull W2p[16], W3p[16];
#pragma unroll
    for (int i = 0; i < 16; i++) {
        W2p[i] = pack2(__ldg(&W2[(2 * i) * 32 + j]), __ldg(&W2[(2 * i + 1) * 32 + j]));
        W3p[i] = pack2(__ldg(&W3[(2 * i) * 32 + j]), __ldg(&W3[(2 * i + 1) * 32 + j]));
    }
    float b2j = __ldg(&b2[j]);
    float b3j = __ldg(&b3[j]);

    uint32_t bx = smem_u32(&bufx[w][0]);
    uint32_t by = smem_u32(&bufy[w][0]);
    uint32_t bxj = bx + 4 * j;
    uint32_t byj = by + 4 * j;

    int b = blockIdx.x * 2 + w;  // one chain per warp
    size_t base = ((size_t)b * TT) * 32 + j;
    const float* Ap = g_A + base;
    const float* Gp = gumbel + base;
    float* Op = out + base;

    int i0 = 0, i1 = 0, i2 = 0, i3 = 0;  // initial c = one_hot(0) per group

    // depth-2 parity register prefetch
    float a_buf[2], g_buf[2];
    a_buf[0] = Ap[0];
    g_buf[0] = Gp[0];
    a_buf[1] = Ap[32];
    g_buf[1] = Gp[32];

#pragma unroll 1
    for (int t = 0; t < TT; t += 2) {
#pragma unroll
        for (int par = 0; par < 2; par++) {
            int tn = t + par + 2;
            if (tn > TT - 1) tn = TT - 1;  // clamped redundant refill, no branch

            // fc1 (+relu) consumes a_buf[par]; stage h1
            float h1 = a_buf[par] + W1c[i0 * 32 + j] + W1c[(8 + i1) * 32 + j] +
                       W1c[(16 + i2) * 32 + j] + W1c[(24 + i3) * 32 + j];
            h1 = fmaxf(h1, 0.0f);
            sts_f32(bxj, h1);
            a_buf[par] = Ap[tn * 32];  // refill: 2 full steps of cover
            __syncwarp();

            // fc2 (+relu), stage h2
            float h2 = fmaxf(matvec32(bx, W2p, b2j), 0.0f);
            sts_f32(byj, h2);
            __syncwarp();

            // fc3 + gumbel (softmax & /tau strictly monotone -> argmax only)
            float v = matvec32(by, W3p, b3j) + g_buf[par];
            g_buf[par] = Gp[tn * 32];  // refill after use (WAR-safe)

            // per-8-lane-group max: fmax butterfly (exact), then one ballot
            float m = v;
            m = fmaxf(m, __shfl_xor_sync(FULL, m, 4));
            m = fmaxf(m, __shfl_xor_sync(FULL, m, 2));
            m = fmaxf(m, __shfl_xor_sync(FULL, m, 1));
            unsigned bal = __ballot_sync(FULL, v == m);

            int win = __ffs((bal >> gsh) & 0xFFu) - 1;  // lowest lane = first index
            // straight-through forward == exact hard one-hot
            Op[(t + par) * 32] = (win == jg) ? 1.0f : 0.0f;

            // all 4 group winners from the uniform ballot (no broadcast shfls)
            i0 = __ffs(bal & 0xFFu) - 1;
            i1 = __ffs((bal >> 8) & 0xFFu) - 1;
            i2 = __ffs((bal >> 16) & 0xFFu) - 1;
            i3 = __ffs((bal >> 24) & 0xFFu) - 1;
        }
    }
}

// ============================================================================
// Launch
// ============================================================================
extern "C" void kernel_launch(void* const* d_in, const int* in_sizes, int n_in,
                              void* d_out, int out_size) {
    const float* states = (const float*)d_in[0];  // [B,T,64]
    const float* gumbel = (const float*)d_in[1];  // [B,T,4,8]
    // d_in[2] = tau (unused: monotone under argmax)
    const float* W1     = (const float*)d_in[3];  // [96,32]
    const float* b1     = (const float*)d_in[4];  // [32]
    const float* W2     = (const float*)d_in[5];  // [32,32]
    const float* b2     = (const float*)d_in[6];  // [32]
    const float* W3     = (const float*)d_in[7];  // [32,32]
    const float* b3     = (const float*)d_in[8];  // [32]
    float* out = (float*)d_out;                   // [B,T,32]

    precompute_kernel<<<BT / PT_ROWS, 256>>>(states, W1, b1);
    recur_kernel<<<BB / 2, 64>>>(gumbel, W1, W2, b2, W3, b3, out);
}